// round 3
// baseline (speedup 1.0000x reference)
#include <cuda_runtime.h>
#include <cuda_bf16.h>

// SurfEval fused single-kernel.
// B=16, M=N=64, deg=3, OUT=256x256, out dim 3 (ctrl has 4 ch, w unused).
// Reference quirks preserved:
//   * V basis is built from knot_u (knot_v is a dead input).
//   * span = argmin over cand = (t-K[3+s] > 1e-8) ? d : 1.0, first-min tie-break.
//   * Cox-de Boor denominator written as (K1 - t) + (t - K2).
//
// Factorization: surf(u,v) = sum_l nu[l]*S_{iu0+l}(v),  S_m(v)=sum_r nv[r]*ctrl[m][iv0+r]
// Block = (u-tile of 4, batch); thread = v. Sliding 4-entry register ring of S_m.
// Compact ctrl window in static smem (max 16 rows; actual need <= ~8 given
// knot increments in [0.5, 1.5] -> min interval >= 0.5/92 > 3*du).

#define BSZ    16
#define MC     64
#define NC     64
#define DEG    3
#define LK     (MC + DEG + 1)   // 68
#define OUTN   256
#define TILE_U 4                // grid.x = 64
#define WROWS  16               // compact window capacity (16 KB)

__device__ __forceinline__ float param_t(int idx)
{
    const float step = (1.0f - 2e-5f) / (float)(OUTN - 1);
    return 1e-5f + (float)idx * step;
}

__device__ __forceinline__ void basis_at(float t, const float* __restrict__ U,
                                         float nb[4], int* span_out)
{
    float best = 1.0f;
    int bs = 0;
    #pragma unroll 1
    for (int s = 0; s < LK - 2 * DEG; s++) {
        const float d = t - U[DEG + s];
        const float cand = (d > 1e-8f) ? d : 1.0f;
        if (cand < best) { best = cand; bs = s; }     // strict < = first min
    }
    const int span = bs + DEG;

    nb[0] = 1.0f; nb[1] = 0.f; nb[2] = 0.f; nb[3] = 0.f;
    #pragma unroll
    for (int k = 1; k <= DEG; k++) {
        float saved = 0.0f;
        #pragma unroll
        for (int r = 0; r < k; r++) {
            const float K1 = U[span + r + 1];
            const float K2 = U[span + 1 - k + r];
            const float temp = nb[r] / ((K1 - t) + (t - K2));
            nb[r] = saved + (K1 - t) * temp;
            saved = (t - K2) * temp;
        }
        nb[k] = saved;
    }
    *span_out = span;
}

__global__ __launch_bounds__(256)
void surfeval_fused(const float4* __restrict__ ctrl,
                    const float*  __restrict__ knot_u,
                    float* __restrict__ out)
{
    __shared__ float4 win[WROWS * NC];    // 16 KB compact ctrl window
    __shared__ float  U[LK];
    __shared__ float  nub[TILE_U][4];
    __shared__ int    ius[TILE_U];

    const int b   = blockIdx.y;
    const int u0  = blockIdx.x * TILE_U;
    const int tid = threadIdx.x;          // = v

    // ---- normalized knots ----
    if (tid == 0) {
        float cs[LK];
        float c = 0.f;
        #pragma unroll 1
        for (int i = 0; i < LK; i++) { c += knot_u[b * LK + i]; cs[i] = c; }
        const float c0  = cs[0];
        const float inv = 1.0f / (cs[LK - 1] - c0);
        #pragma unroll 1
        for (int i = 0; i < LK; i++) U[i] = (cs[i] - c0) * inv;
    }
    __syncthreads();

    // ---- basis for this thread's v ----
    float nv[4]; int vspan;
    basis_at(param_t(tid), U, nv, &vspan);
    const int iv0 = vspan - DEG;

    // ---- basis for the tile's 4 u rows ----
    if (tid < TILE_U) {
        float nb[4]; int sp;
        basis_at(param_t(u0 + tid), U, nb, &sp);
        ius[tid] = sp - DEG;
        #pragma unroll
        for (int l = 0; l < 4; l++) nub[tid][l] = nb[l];
    }
    __syncthreads();

    // ---- window bounds (each thread; 4 smem reads, no reduction needed) ----
    int mlo = ius[0], mhi = ius[0];
    #pragma unroll
    for (int i = 1; i < TILE_U; i++) {
        mlo = min(mlo, ius[i]); mhi = max(mhi, ius[i]);
    }
    mhi += DEG;
    int nrows = mhi - mlo + 1;
    if (nrows > WROWS) nrows = WROWS;     // safety clamp (never hit for this data)

    // ---- cooperative compact load: nrows*64 float4, <= 2 per thread ----
    for (int idx = tid; idx < nrows * NC; idx += 256) {
        win[idx] = ctrl[((size_t)b * MC + mlo) * NC + idx];
    }
    __syncthreads();

    // ---- sliding-window evaluation over 4 u rows ----
    float3 S0, S1, S2, S3;                // ring slots, slot = m & 3
    int mtop = mlo - 1;                   // highest m with S computed

    float* op = out + (((size_t)(b * OUTN + u0) * OUTN) + tid) * 3;

    #pragma unroll 1
    for (int uu = 0; uu < TILE_U; uu++) {
        const int iu0 = ius[uu];
        if (mtop < iu0 - 1 || mtop > iu0 + 3) mtop = iu0 - 1;  // safety reseed
        while (mtop < iu0 + 3) {
            mtop++;
            float sx = 0.f, sy = 0.f, sz = 0.f;
            const float4* wrow = &win[(mtop - mlo) * NC + iv0];
            #pragma unroll
            for (int r = 0; r < 4; r++) {
                const float4 cp = wrow[r];
                sx = fmaf(nv[r], cp.x, sx);
                sy = fmaf(nv[r], cp.y, sy);
                sz = fmaf(nv[r], cp.z, sz);
            }
            const int slot = mtop & 3;
            if      (slot == 0) S0 = make_float3(sx, sy, sz);
            else if (slot == 1) S1 = make_float3(sx, sy, sz);
            else if (slot == 2) S2 = make_float3(sx, sy, sz);
            else                S3 = make_float3(sx, sy, sz);
        }

        // weight for ring slot s is nu[(s - iu0) mod 4]
        const float w0 = nub[uu][(0 - iu0) & 3];
        const float w1 = nub[uu][(1 - iu0) & 3];
        const float w2 = nub[uu][(2 - iu0) & 3];
        const float w3 = nub[uu][(3 - iu0) & 3];

        op[0] = fmaf(w0, S0.x, fmaf(w1, S1.x, fmaf(w2, S2.x, w3 * S3.x)));
        op[1] = fmaf(w0, S0.y, fmaf(w1, S1.y, fmaf(w2, S2.y, w3 * S3.y)));
        op[2] = fmaf(w0, S0.z, fmaf(w1, S1.z, fmaf(w2, S2.z, w3 * S3.z)));
        op += OUTN * 3;
    }
}

// ---------------------------------------------------------------------------
extern "C" void kernel_launch(void* const* d_in, const int* in_sizes, int n_in,
                              void* d_out, int out_size)
{
    const float4* ctrl   = (const float4*)d_in[0];   // [16,64,64,4] f32
    const float*  knot_u = (const float*)d_in[1];    // [16,68] f32
    // d_in[2] (knot_v) unused: reference builds V from knot_u
    float* out = (float*)d_out;                      // [16,256,256,3] f32

    dim3 grid(OUTN / TILE_U, BSZ);                   // 64 x 16 = 1024 blocks
    surfeval_fused<<<grid, 256>>>(ctrl, knot_u, out);
}

// round 4
// speedup vs baseline: 1.7267x; 1.7267x over previous
#include <cuda_runtime.h>
#include <cuda_bf16.h>

// SurfEval: two-kernel (basis precompute + sliding-window eval).
// B=16, M=N=64, deg=3, OUT=256x256, out dim 3 (ctrl has 4 ch, w unused).
// Reference quirks preserved:
//   * V basis is built from knot_u (knot_v is a dead input) -> Nv==Nu, vspan==uspan.
//   * span = argmin over cand = (t-K[3+s] > 1e-8) ? d : 1.0, first-min tie-break.
//     U strictly increasing => d monotone decreasing => argmin = largest s with
//     d > 1e-8 (or s=0 if none) => 6-step binary search, identical result.
//   * Cox-de Boor denominator written as (K1 - t) + (t - K2).

#define BSZ    16
#define MC     64
#define NC     64
#define DEG    3
#define LK     (MC + DEG + 1)   // 68
#define OUTN   256
#define TILE_U 4                // eval grid.x = 64
#define WROWS  16               // compact ctrl window capacity (16 KB)

__device__ float4 g_basis[BSZ * OUTN];   // [b][i] -> N0..N3
__device__ int    g_span [BSZ * OUTN];

__device__ __forceinline__ float param_t(int idx)
{
    const float step = (1.0f - 2e-5f) / (float)(OUTN - 1);
    return 1e-5f + (float)idx * step;
}

// ---------------------------------------------------------------------------
// Kernel A: per-batch normalized knots + span (binary search) + Cox-de Boor.
// Grid: 16 blocks (batch), 256 threads (eval parameter).
// ---------------------------------------------------------------------------
__global__ void surfeval_basis_kernel(const float* __restrict__ knot_u)
{
    __shared__ float U[LK];
    const int b = blockIdx.x;

    if (threadIdx.x == 0) {
        float cs[LK];
        float c = 0.f;
        #pragma unroll 1
        for (int i = 0; i < LK; i++) { c += knot_u[b * LK + i]; cs[i] = c; }
        const float c0  = cs[0];
        const float inv = 1.0f / (cs[LK - 1] - c0);
        #pragma unroll 1
        for (int i = 0; i < LK; i++) U[i] = (cs[i] - c0) * inv;
    }
    __syncthreads();

    const int i = threadIdx.x;
    const float t = param_t(i);

    // binary search: largest s in [0, 61] with (t - U[3+s]) > 1e-8; 0 if none
    int lo = 0, hi = LK - 2 * DEG - 1;           // [0, 61]
    if (!(t - U[DEG] > 1e-8f)) {
        lo = 0;                                   // no valid span -> first index
    } else {
        while (lo < hi) {
            const int mid = (lo + hi + 1) >> 1;
            if (t - U[DEG + mid] > 1e-8f) lo = mid; else hi = mid - 1;
        }
    }
    const int span = lo + DEG;

    // Cox-de Boor (deg 3), exact expression order of the reference
    float nb[DEG + 1];
    nb[0] = 1.0f; nb[1] = 0.f; nb[2] = 0.f; nb[3] = 0.f;
    #pragma unroll
    for (int k = 1; k <= DEG; k++) {
        float saved = 0.0f;
        #pragma unroll
        for (int r = 0; r < k; r++) {
            const float K1 = U[span + r + 1];
            const float K2 = U[span + 1 - k + r];
            const float temp = nb[r] / ((K1 - t) + (t - K2));
            nb[r] = saved + (K1 - t) * temp;
            saved = (t - K2) * temp;
        }
        nb[k] = saved;
    }

    g_span [b * OUTN + i] = span;
    g_basis[b * OUTN + i] = make_float4(nb[0], nb[1], nb[2], nb[3]);
}

// ---------------------------------------------------------------------------
// Kernel B: sliding-window eval. Block = (u-tile of 4, batch), thread = v.
// surf(u,v) = sum_l nu[l]*S_{iu0+l}(v), S_m(v) = sum_r nv[r]*ctrl[m][iv0+r].
// 4-entry register ring of S_m shared across the 4 u rows (spans monotone).
// ---------------------------------------------------------------------------
__global__ __launch_bounds__(256)
void surfeval_eval_kernel(const float4* __restrict__ ctrl,
                          float* __restrict__ out)
{
    __shared__ float4 win[WROWS * NC];    // 16 KB compact ctrl window
    __shared__ float  nub[TILE_U][4];
    __shared__ int    ius[TILE_U];

    const int b   = blockIdx.y;
    const int u0  = blockIdx.x * TILE_U;
    const int tid = threadIdx.x;          // = v

    if (tid < TILE_U) {
        const float4 nb = g_basis[b * OUTN + u0 + tid];
        ius[tid] = g_span[b * OUTN + u0 + tid] - DEG;
        nub[tid][0] = nb.x; nub[tid][1] = nb.y;
        nub[tid][2] = nb.z; nub[tid][3] = nb.w;
    }

    // this thread's v basis (L2-hot global reads)
    const int   iv0 = g_span[b * OUTN + tid] - DEG;
    const float4 nvv = g_basis[b * OUTN + tid];
    const float nv0 = nvv.x, nv1 = nvv.y, nv2 = nvv.z, nv3 = nvv.w;
    __syncthreads();

    // window bounds (per-thread; 4 smem reads)
    int mlo = ius[0], mhi = ius[0];
    #pragma unroll
    for (int i = 1; i < TILE_U; i++) {
        mlo = min(mlo, ius[i]); mhi = max(mhi, ius[i]);
    }
    mhi += DEG;
    int nrows = mhi - mlo + 1;
    if (nrows > WROWS) nrows = WROWS;     // safety clamp (never hit here)

    // cooperative compact window load: nrows*64 float4 (<= 2 per thread)
    for (int idx = tid; idx < nrows * NC; idx += 256) {
        win[idx] = ctrl[((size_t)b * MC + mlo) * NC + idx];
    }
    __syncthreads();

    float3 S0, S1, S2, S3;                // ring slots, slot = m & 3
    int mtop = mlo - 1;                   // highest m with S computed

    float* op = out + (((size_t)(b * OUTN + u0) * OUTN) + tid) * 3;

    #pragma unroll 1
    for (int uu = 0; uu < TILE_U; uu++) {
        const int iu0 = ius[uu];
        if (mtop < iu0 - 1 || mtop > iu0 + 3) mtop = iu0 - 1;  // safety reseed
        while (mtop < iu0 + 3) {
            mtop++;
            const float4* wrow = &win[(mtop - mlo) * NC + iv0];
            const float4 c0 = wrow[0], c1 = wrow[1], c2 = wrow[2], c3 = wrow[3];
            float sx = fmaf(nv0, c0.x, fmaf(nv1, c1.x, fmaf(nv2, c2.x, nv3 * c3.x)));
            float sy = fmaf(nv0, c0.y, fmaf(nv1, c1.y, fmaf(nv2, c2.y, nv3 * c3.y)));
            float sz = fmaf(nv0, c0.z, fmaf(nv1, c1.z, fmaf(nv2, c2.z, nv3 * c3.z)));
            const int slot = mtop & 3;
            if      (slot == 0) S0 = make_float3(sx, sy, sz);
            else if (slot == 1) S1 = make_float3(sx, sy, sz);
            else if (slot == 2) S2 = make_float3(sx, sy, sz);
            else                S3 = make_float3(sx, sy, sz);
        }

        // weight for ring slot s is nu[(s - iu0) mod 4]
        const float w0 = nub[uu][(0 - iu0) & 3];
        const float w1 = nub[uu][(1 - iu0) & 3];
        const float w2 = nub[uu][(2 - iu0) & 3];
        const float w3 = nub[uu][(3 - iu0) & 3];

        op[0] = fmaf(w0, S0.x, fmaf(w1, S1.x, fmaf(w2, S2.x, w3 * S3.x)));
        op[1] = fmaf(w0, S0.y, fmaf(w1, S1.y, fmaf(w2, S2.y, w3 * S3.y)));
        op[2] = fmaf(w0, S0.z, fmaf(w1, S1.z, fmaf(w2, S2.z, w3 * S3.z)));
        op += OUTN * 3;
    }
}

// ---------------------------------------------------------------------------
extern "C" void kernel_launch(void* const* d_in, const int* in_sizes, int n_in,
                              void* d_out, int out_size)
{
    const float4* ctrl   = (const float4*)d_in[0];   // [16,64,64,4] f32
    const float*  knot_u = (const float*)d_in[1];    // [16,68] f32
    // d_in[2] (knot_v) unused: reference builds V from knot_u
    float* out = (float*)d_out;                      // [16,256,256,3] f32

    surfeval_basis_kernel<<<BSZ, OUTN>>>(knot_u);
    dim3 grid(OUTN / TILE_U, BSZ);                   // 64 x 16 = 1024 blocks
    surfeval_eval_kernel<<<grid, 256>>>(ctrl, out);
}

// round 5
// speedup vs baseline: 2.0392x; 1.1810x over previous
#include <cuda_runtime.h>
#include <cuda_bf16.h>

// SurfEval: two-kernel (basis precompute + sliding-window eval).
// B=16, M=N=64, deg=3, OUT=256x256, out dim 3 (ctrl has 4 ch, w unused).
// Reference quirks preserved:
//   * V basis is built from knot_u (knot_v is a dead input) -> Nv==Nu, vspan==uspan.
//   * span = argmin over cand = (t-K[3+s] > 1e-8) ? d : 1.0, first-min tie-break.
//     U strictly increasing => d monotone decreasing => argmin = largest s with
//     d > 1e-8 (or s=0 if none) => 6-step binary search, identical result.
//   * Cox-de Boor denominator written as (K1 - t) + (t - K2).
//   * cumsum kept sequential (thread 0) over SMEM to preserve FP order;
//     the global->smem staging is cooperative/coalesced so only ONE global
//     round-trip is paid instead of 68 serial ones.

#define BSZ    16
#define MC     64
#define NC     64
#define DEG    3
#define LK     (MC + DEG + 1)   // 68
#define OUTN   256
#define TILE_U 8                // eval grid.x = 32 -> 512 blocks
#define WROWS  16               // compact ctrl window capacity (16 KB)

__device__ float4 g_basis[BSZ * OUTN];   // [b][i] -> N0..N3
__device__ int    g_span [BSZ * OUTN];

__device__ __forceinline__ float param_t(int idx)
{
    const float step = (1.0f - 2e-5f) / (float)(OUTN - 1);
    return 1e-5f + (float)idx * step;
}

// ---------------------------------------------------------------------------
// Kernel A: per-batch normalized knots + span (binary search) + Cox-de Boor.
// Grid: 16 blocks (batch), 256 threads (eval parameter).
// ---------------------------------------------------------------------------
__global__ void surfeval_basis_kernel(const float* __restrict__ knot_u)
{
    __shared__ float raw[LK];
    __shared__ float U[LK];
    const int b = blockIdx.x;
    const int i = threadIdx.x;

    // cooperative coalesced stage of the 68 raw knots
    if (i < LK) raw[i] = knot_u[b * LK + i];
    __syncthreads();

    // sequential cumsum over SMEM (exact reference FP order), then normalize
    if (i == 0) {
        float c = 0.f;
        #pragma unroll 1
        for (int j = 0; j < LK; j++) { c += raw[j]; U[j] = c; }
        const float c0  = U[0];
        const float inv = 1.0f / (U[LK - 1] - c0);
        #pragma unroll 1
        for (int j = 0; j < LK; j++) U[j] = (U[j] - c0) * inv;
    }
    __syncthreads();

    const float t = param_t(i);

    // binary search: largest s in [0, 61] with (t - U[3+s]) > 1e-8; 0 if none
    int lo = 0, hi = LK - 2 * DEG - 1;           // [0, 61]
    if (!(t - U[DEG] > 1e-8f)) {
        lo = 0;
    } else {
        while (lo < hi) {
            const int mid = (lo + hi + 1) >> 1;
            if (t - U[DEG + mid] > 1e-8f) lo = mid; else hi = mid - 1;
        }
    }
    const int span = lo + DEG;

    // Cox-de Boor (deg 3), exact expression order of the reference
    float nb[DEG + 1];
    nb[0] = 1.0f; nb[1] = 0.f; nb[2] = 0.f; nb[3] = 0.f;
    #pragma unroll
    for (int k = 1; k <= DEG; k++) {
        float saved = 0.0f;
        #pragma unroll
        for (int r = 0; r < k; r++) {
            const float K1 = U[span + r + 1];
            const float K2 = U[span + 1 - k + r];
            const float temp = nb[r] / ((K1 - t) + (t - K2));
            nb[r] = saved + (K1 - t) * temp;
            saved = (t - K2) * temp;
        }
        nb[k] = saved;
    }

    g_span [b * OUTN + i] = span;
    g_basis[b * OUTN + i] = make_float4(nb[0], nb[1], nb[2], nb[3]);
}

// ---------------------------------------------------------------------------
// Kernel B: sliding-window eval. Block = (u-tile of 8, batch), thread = v.
// surf(u,v) = sum_l nu[l]*S_{iu0+l}(v), S_m(v) = sum_r nv[r]*ctrl[m][iv0+r].
// 4-entry register ring of S_m shared across the 8 u rows (spans monotone):
// ~7 S-computes per 8 output points instead of 32.
// ---------------------------------------------------------------------------
__global__ __launch_bounds__(256)
void surfeval_eval_kernel(const float4* __restrict__ ctrl,
                          float* __restrict__ out)
{
    __shared__ float4 win[WROWS * NC];    // 16 KB compact ctrl window
    __shared__ float  nub[TILE_U][4];
    __shared__ int    ius[TILE_U];

    const int b   = blockIdx.y;
    const int u0  = blockIdx.x * TILE_U;
    const int tid = threadIdx.x;          // = v

    if (tid < TILE_U) {
        const float4 nb = g_basis[b * OUTN + u0 + tid];
        ius[tid] = g_span[b * OUTN + u0 + tid] - DEG;
        nub[tid][0] = nb.x; nub[tid][1] = nb.y;
        nub[tid][2] = nb.z; nub[tid][3] = nb.w;
    }

    // this thread's v basis (L2-hot global reads)
    const int   iv0 = g_span[b * OUTN + tid] - DEG;
    const float4 nvv = g_basis[b * OUTN + tid];
    const float nv0 = nvv.x, nv1 = nvv.y, nv2 = nvv.z, nv3 = nvv.w;
    __syncthreads();

    // window bounds (per-thread; TILE_U smem reads)
    int mlo = ius[0], mhi = ius[TILE_U - 1];
    #pragma unroll
    for (int i = 1; i < TILE_U; i++) {
        mlo = min(mlo, ius[i]); mhi = max(mhi, ius[i]);
    }
    mhi += DEG;
    int nrows = mhi - mlo + 1;
    if (nrows > WROWS) nrows = WROWS;     // safety clamp (never hit here)

    // cooperative compact window load: nrows*64 float4 (<= 3 per thread)
    for (int idx = tid; idx < nrows * NC; idx += 256) {
        win[idx] = ctrl[((size_t)b * MC + mlo) * NC + idx];
    }
    __syncthreads();

    float3 S0, S1, S2, S3;                // ring slots, slot = m & 3
    int mtop = mlo - 1;                   // highest m with S computed

    float* op = out + (((size_t)(b * OUTN + u0) * OUTN) + tid) * 3;

    #pragma unroll 1
    for (int uu = 0; uu < TILE_U; uu++) {
        const int iu0 = ius[uu];
        if (mtop < iu0 - 1 || mtop > iu0 + 3) mtop = iu0 - 1;  // safety reseed
        while (mtop < iu0 + 3) {
            mtop++;
            const float4* wrow = &win[(mtop - mlo) * NC + iv0];
            const float4 c0 = wrow[0], c1 = wrow[1], c2 = wrow[2], c3 = wrow[3];
            float sx = fmaf(nv0, c0.x, fmaf(nv1, c1.x, fmaf(nv2, c2.x, nv3 * c3.x)));
            float sy = fmaf(nv0, c0.y, fmaf(nv1, c1.y, fmaf(nv2, c2.y, nv3 * c3.y)));
            float sz = fmaf(nv0, c0.z, fmaf(nv1, c1.z, fmaf(nv2, c2.z, nv3 * c3.z)));
            const int slot = mtop & 3;
            if      (slot == 0) S0 = make_float3(sx, sy, sz);
            else if (slot == 1) S1 = make_float3(sx, sy, sz);
            else if (slot == 2) S2 = make_float3(sx, sy, sz);
            else                S3 = make_float3(sx, sy, sz);
        }

        // weight for ring slot s is nu[(s - iu0) mod 4]
        const float w0 = nub[uu][(0 - iu0) & 3];
        const float w1 = nub[uu][(1 - iu0) & 3];
        const float w2 = nub[uu][(2 - iu0) & 3];
        const float w3 = nub[uu][(3 - iu0) & 3];

        op[0] = fmaf(w0, S0.x, fmaf(w1, S1.x, fmaf(w2, S2.x, w3 * S3.x)));
        op[1] = fmaf(w0, S0.y, fmaf(w1, S1.y, fmaf(w2, S2.y, w3 * S3.y)));
        op[2] = fmaf(w0, S0.z, fmaf(w1, S1.z, fmaf(w2, S2.z, w3 * S3.z)));
        op += OUTN * 3;
    }
}

// ---------------------------------------------------------------------------
extern "C" void kernel_launch(void* const* d_in, const int* in_sizes, int n_in,
                              void* d_out, int out_size)
{
    const float4* ctrl   = (const float4*)d_in[0];   // [16,64,64,4] f32
    const float*  knot_u = (const float*)d_in[1];    // [16,68] f32
    // d_in[2] (knot_v) unused: reference builds V from knot_u
    float* out = (float*)d_out;                      // [16,256,256,3] f32

    surfeval_basis_kernel<<<BSZ, OUTN>>>(knot_u);
    dim3 grid(OUTN / TILE_U, BSZ);                   // 32 x 16 = 512 blocks
    surfeval_eval_kernel<<<grid, 256>>>(ctrl, out);
}

// round 6
// speedup vs baseline: 3.7143x; 1.8214x over previous
#include <cuda_runtime.h>
#include <cuda_bf16.h>

// SurfEval: single fused kernel.
// B=16, M=N=64, deg=3, OUT=256x256, out dim 3 (ctrl has 4 ch, w unused).
// Reference quirks preserved:
//   * V basis is built from knot_u (knot_v is a dead input) -> Nv==Nu, vspan==uspan.
//   * span = argmin over cand = (t-K[3+s] > 1e-8) ? d : 1.0, first-min tie-break.
//     U strictly increasing => argmin = largest s with d > 1e-8 (0 if none)
//     => 6-step binary search, identical result.
//   * Cox-de Boor denominator written as (K1 - t) + (t - K2).
//   * cumsum: thread-0 sequential adds in reference order, but over SMEM with
//     the loop fully unrolled (batched LDS + 4-cyc FADD chain), after a
//     cooperative coalesced global stage. Bit-identical FP result.
//
// Eval: surf(u,v) = sum_l nu[l]*S_{iu0+l}(v), S_m(v) = sum_r nv[r]*ctrl[m][iv0+r].
// Block = (u-tile of 8, batch); thread = v. 4-entry register ring of S_m slides
// across the 8 u rows (spans monotone): ~7 S-computes per 8 outputs.

#define BSZ    16
#define MC     64
#define NC     64
#define DEG    3
#define LK     (MC + DEG + 1)   // 68
#define OUTN   256
#define TILE_U 8                // grid.x = 32 -> 512 blocks
#define WROWS  16               // compact ctrl window capacity (16 KB)

__device__ __forceinline__ float param_t(int idx)
{
    const float step = (1.0f - 2e-5f) / (float)(OUTN - 1);
    return 1e-5f + (float)idx * step;
}

// find_span (binary search, equivalent to reference argmin) + Cox-de Boor.
__device__ __forceinline__ void basis_at(float t, const float* __restrict__ U,
                                         float nb[4], int* iu0_out)
{
    int lo = 0, hi = LK - 2 * DEG - 1;           // s in [0, 61]
    if (!(t - U[DEG] > 1e-8f)) {
        lo = 0;
    } else {
        #pragma unroll
        for (int step = 0; step < 6; step++) {   // ceil(log2(62)) = 6
            if (lo < hi) {
                const int mid = (lo + hi + 1) >> 1;
                if (t - U[DEG + mid] > 1e-8f) lo = mid; else hi = mid - 1;
            }
        }
    }
    const int span = lo + DEG;

    nb[0] = 1.0f; nb[1] = 0.f; nb[2] = 0.f; nb[3] = 0.f;
    #pragma unroll
    for (int k = 1; k <= DEG; k++) {
        float saved = 0.0f;
        #pragma unroll
        for (int r = 0; r < k; r++) {
            const float K1 = U[span + r + 1];
            const float K2 = U[span + 1 - k + r];
            const float temp = nb[r] / ((K1 - t) + (t - K2));
            nb[r] = saved + (K1 - t) * temp;
            saved = (t - K2) * temp;
        }
        nb[k] = saved;
    }
    *iu0_out = span - DEG;
}

__global__ __launch_bounds__(256)
void surfeval_fused(const float4* __restrict__ ctrl,
                    const float*  __restrict__ knot_u,
                    float* __restrict__ out)
{
    __shared__ float4 win[WROWS * NC];    // 16 KB compact ctrl window
    __shared__ float  U[LK];
    __shared__ float  nub[TILE_U][4];
    __shared__ int    ius[TILE_U];
    __shared__ float  norm_c0, norm_inv;

    const int b   = blockIdx.y;
    const int u0  = blockIdx.x * TILE_U;
    const int tid = threadIdx.x;          // = v

    // ---- stage raw knots (coalesced, L2-hot) ----
    if (tid < LK) U[tid] = knot_u[b * LK + tid];
    __syncthreads();

    // ---- sequential cumsum over SMEM, fully unrolled (reference FP order) ----
    if (tid == 0) {
        float c = 0.f;
        #pragma unroll
        for (int j = 0; j < LK; j++) { c += U[j]; U[j] = c; }
        norm_c0  = U[0];
        norm_inv = 1.0f / (U[LK - 1] - U[0]);
    }
    __syncthreads();

    // ---- parallel normalize (per-element in-place, race-free) ----
    if (tid < LK) U[tid] = (U[tid] - norm_c0) * norm_inv;
    __syncthreads();

    // ---- basis for this thread's v ----
    float nv[4]; int iv0;
    basis_at(param_t(tid), U, nv, &iv0);
    const float nv0 = nv[0], nv1 = nv[1], nv2 = nv[2], nv3 = nv[3];

    // ---- basis for the tile's 8 u rows ----
    if (tid < TILE_U) {
        float nb[4]; int iu;
        basis_at(param_t(u0 + tid), U, nb, &iu);
        ius[tid] = iu;
        nub[tid][0] = nb[0]; nub[tid][1] = nb[1];
        nub[tid][2] = nb[2]; nub[tid][3] = nb[3];
    }
    __syncthreads();

    // ---- window bounds (per-thread; TILE_U smem reads) ----
    int mlo = ius[0], mhi = ius[0];
    #pragma unroll
    for (int i = 1; i < TILE_U; i++) {
        mlo = min(mlo, ius[i]); mhi = max(mhi, ius[i]);
    }
    mhi += DEG;
    int nrows = mhi - mlo + 1;
    if (nrows > WROWS) nrows = WROWS;     // safety clamp (never hit here)

    // ---- cooperative compact window load: nrows*64 float4 (<= 3/thread) ----
    for (int idx = tid; idx < nrows * NC; idx += 256) {
        win[idx] = ctrl[((size_t)b * MC + mlo) * NC + idx];
    }
    __syncthreads();

    // ---- sliding-window evaluation over 8 u rows ----
    float3 S0, S1, S2, S3;                // ring slots, slot = m & 3
    int mtop = mlo - 1;                   // highest m with S computed

    float* op = out + (((size_t)(b * OUTN + u0) * OUTN) + tid) * 3;

    #pragma unroll 1
    for (int uu = 0; uu < TILE_U; uu++) {
        const int iu0 = ius[uu];
        if (mtop < iu0 - 1 || mtop > iu0 + 3) mtop = iu0 - 1;  // safety reseed
        while (mtop < iu0 + 3) {
            mtop++;
            const float4* wrow = &win[(mtop - mlo) * NC + iv0];
            const float4 c0 = wrow[0], c1 = wrow[1], c2 = wrow[2], c3 = wrow[3];
            float sx = fmaf(nv0, c0.x, fmaf(nv1, c1.x, fmaf(nv2, c2.x, nv3 * c3.x)));
            float sy = fmaf(nv0, c0.y, fmaf(nv1, c1.y, fmaf(nv2, c2.y, nv3 * c3.y)));
            float sz = fmaf(nv0, c0.z, fmaf(nv1, c1.z, fmaf(nv2, c2.z, nv3 * c3.z)));
            const int slot = mtop & 3;
            if      (slot == 0) S0 = make_float3(sx, sy, sz);
            else if (slot == 1) S1 = make_float3(sx, sy, sz);
            else if (slot == 2) S2 = make_float3(sx, sy, sz);
            else                S3 = make_float3(sx, sy, sz);
        }

        // weight for ring slot s is nu[(s - iu0) mod 4]
        const float w0 = nub[uu][(0 - iu0) & 3];
        const float w1 = nub[uu][(1 - iu0) & 3];
        const float w2 = nub[uu][(2 - iu0) & 3];
        const float w3 = nub[uu][(3 - iu0) & 3];

        op[0] = fmaf(w0, S0.x, fmaf(w1, S1.x, fmaf(w2, S2.x, w3 * S3.x)));
        op[1] = fmaf(w0, S0.y, fmaf(w1, S1.y, fmaf(w2, S2.y, w3 * S3.y)));
        op[2] = fmaf(w0, S0.z, fmaf(w1, S1.z, fmaf(w2, S2.z, w3 * S3.z)));
        op += OUTN * 3;
    }
}

// ---------------------------------------------------------------------------
extern "C" void kernel_launch(void* const* d_in, const int* in_sizes, int n_in,
                              void* d_out, int out_size)
{
    const float4* ctrl   = (const float4*)d_in[0];   // [16,64,64,4] f32
    const float*  knot_u = (const float*)d_in[1];    // [16,68] f32
    // d_in[2] (knot_v) unused: reference builds V from knot_u
    float* out = (float*)d_out;                      // [16,256,256,3] f32

    dim3 grid(OUTN / TILE_U, BSZ);                   // 32 x 16 = 512 blocks
    surfeval_fused<<<grid, 256>>>(ctrl, knot_u, out);
}